// round 1
// baseline (speedup 1.0000x reference)
#include <cuda_runtime.h>
#include <math.h>

#define BSZ 2
#define LSZ 1024
#define DM 768
#define NL 4
#define DI 1536
#define DS 16
#define DTR 48
#define XPN 80          // DTR + 2*DS
#define ROWS (BSZ*LSZ)  // 2048

// ---------------- scratch (device globals; no allocation allowed) ----------
__device__ float g_resid[ROWS * DM];
__device__ float g_hn[ROWS * DM];
__device__ float g_xz[ROWS * 2 * DI];
__device__ float g_xc[ROWS * DI];
__device__ float g_xdbl[ROWS * XPN];
__device__ float g_delta[ROWS * DI];
__device__ float g_y[ROWS * DI];

// ---------------- helpers ----------------
__device__ __forceinline__ float block_sum(float v) {
    __shared__ float sh[8];
    __syncthreads();
#pragma unroll
    for (int o = 16; o; o >>= 1) v += __shfl_xor_sync(0xffffffffu, v, o);
    if ((threadIdx.x & 31) == 0) sh[threadIdx.x >> 5] = v;
    __syncthreads();
    if (threadIdx.x < 32) {
        float t = (threadIdx.x < (blockDim.x >> 5)) ? sh[threadIdx.x] : 0.f;
#pragma unroll
        for (int o = 4; o; o >>= 1) t += __shfl_xor_sync(0xffffffffu, t, o);
        if (threadIdx.x == 0) sh[0] = t;
    }
    __syncthreads();
    return sh[0];
}

// ---------------- embedding gather ----------------
__global__ void embed_k(const int* __restrict__ seq, const float* __restrict__ emb,
                        float* __restrict__ resid) {
    int i = blockIdx.x * blockDim.x + threadIdx.x;   // over ROWS * (DM/4)
    if (i >= ROWS * (DM / 4)) return;
    int row = i / (DM / 4), c4 = i % (DM / 4);
    int tok = seq[row];
    reinterpret_cast<float4*>(resid)[(size_t)row * (DM / 4) + c4] =
        reinterpret_cast<const float4*>(emb)[(size_t)tok * (DM / 4) + c4];
}

// ---------------- rmsnorm (one block per row) ----------------
__global__ void rmsnorm_k(const float* __restrict__ x, const float* __restrict__ w,
                          float* __restrict__ o) {
    int row = blockIdx.x;
    const float* xr = x + (size_t)row * DM;
    float s = 0.f;
    for (int c = threadIdx.x; c < DM; c += blockDim.x) { float v = xr[c]; s += v * v; }
    s = block_sum(s);
    float inv = rsqrtf(s / (float)DM + 1e-5f);
    for (int c = threadIdx.x; c < DM; c += blockDim.x)
        o[(size_t)row * DM + c] = xr[c] * inv * w[c];
}

// ---------------- depthwise causal conv (width 4) + bias + silu ------------
__global__ void conv_silu_k(const float* __restrict__ xz, const float* __restrict__ cw,
                            const float* __restrict__ cb, float* __restrict__ xc) {
    int i = blockIdx.x * blockDim.x + threadIdx.x;  // ROWS*DI
    if (i >= ROWS * DI) return;
    int d = i % DI;
    int row = i / DI;
    int l = row & (LSZ - 1);
    float acc = cb[d];
#pragma unroll
    for (int k = 0; k < 4; k++) {
        int l2 = l + k - 3;
        if (l2 >= 0)
            acc += xz[(size_t)(row + k - 3) * (2 * DI) + d] * cw[d * 4 + k];
    }
    acc = acc / (1.f + __expf(-acc));  // silu
    xc[i] = acc;
}

// ---------------- generic NT GEMM: C[m,n] = sum_k A[m,k]*W[n,k] ------------
// EPI: 0 = store, 1 = softplus(acc + bias[n]), 2 = C += acc
template <int EPI>
__global__ void __launch_bounds__(256) gemm_nt(
    const float* __restrict__ A, const float* __restrict__ W,
    float* __restrict__ C, const float* __restrict__ bias,
    int M, int N, int K, int lda) {
    __shared__ __align__(16) float As[16][64];
    __shared__ __align__(16) float Ws[16][64];
    int tid = threadIdx.x;
    int m0 = blockIdx.y * 64, n0 = blockIdx.x * 64;
    int tm = tid >> 4, tn = tid & 15;
    int lr = tid >> 2;         // 0..63 (row within tile)
    int lk = (tid & 3) * 4;    // 0,4,8,12 (k within tile)
    float acc[4][4] = {};
    for (int k0 = 0; k0 < K; k0 += 16) {
        float4 av = make_float4(0.f, 0.f, 0.f, 0.f);
        float4 wv = make_float4(0.f, 0.f, 0.f, 0.f);
        int am = m0 + lr;
        if (am < M) av = *reinterpret_cast<const float4*>(A + (size_t)am * lda + k0 + lk);
        int wn = n0 + lr;
        if (wn < N) wv = *reinterpret_cast<const float4*>(W + (size_t)wn * K + k0 + lk);
        __syncthreads();
        As[lk + 0][lr] = av.x; As[lk + 1][lr] = av.y;
        As[lk + 2][lr] = av.z; As[lk + 3][lr] = av.w;
        Ws[lk + 0][lr] = wv.x; Ws[lk + 1][lr] = wv.y;
        Ws[lk + 2][lr] = wv.z; Ws[lk + 3][lr] = wv.w;
        __syncthreads();
#pragma unroll
        for (int kk = 0; kk < 16; kk++) {
            float4 a = *reinterpret_cast<const float4*>(&As[kk][tm * 4]);
            float4 w = *reinterpret_cast<const float4*>(&Ws[kk][tn * 4]);
            float ar[4] = {a.x, a.y, a.z, a.w};
            float wr[4] = {w.x, w.y, w.z, w.w};
#pragma unroll
            for (int i = 0; i < 4; i++)
#pragma unroll
                for (int j = 0; j < 4; j++) acc[i][j] += ar[i] * wr[j];
        }
    }
#pragma unroll
    for (int i = 0; i < 4; i++) {
        int m = m0 + tm * 4 + i;
        if (m >= M) continue;
#pragma unroll
        for (int j = 0; j < 4; j++) {
            int n = n0 + tn * 4 + j;
            if (n >= N) continue;
            float v = acc[i][j];
            if (EPI == 1) {
                v += bias[n];
                v = (v > 20.f) ? v : log1pf(__expf(v));
            }
            size_t idx = (size_t)m * N + n;
            if (EPI == 2) C[idx] += v;
            else C[idx] = v;
        }
    }
}

// ---------------- selective scan: 2 channels per warp, 16 states/lane-group -
__global__ void __launch_bounds__(256) scan_k(
    const float* __restrict__ delta, const float* __restrict__ xc,
    const float* __restrict__ xdbl, const float* __restrict__ xz,
    const float* __restrict__ A_log, const float* __restrict__ dski,
    float* __restrict__ y) {
    int warp = (blockIdx.x * blockDim.x + threadIdx.x) >> 5;
    int lane = threadIdx.x & 31;
    int half = lane >> 4;
    int s = lane & 15;
    int c = warp * 2 + half;          // 0..3071 = b*DI + d
    if (c >= BSZ * DI) return;
    int b = c / DI;
    int d = c % DI;

    float As = -__expf(A_log[d * DS + s]);
    float dsk = dski[d];
    float h = 0.f;
    const float* drow = delta + (size_t)b * LSZ * DI + d;
    const float* urow = xc + (size_t)b * LSZ * DI + d;
    const float* zrow = xz + (size_t)b * LSZ * (2 * DI) + DI + d;
    const float* xd = xdbl + (size_t)b * LSZ * XPN;
    float* yrow = y + (size_t)b * LSZ * DI + d;

    // prefetch step 0
    float dl = drow[0];
    float u  = urow[0];
    float bm = xd[DTR + s];
    float cm = xd[DTR + DS + s];
#pragma unroll 4
    for (int l = 0; l < LSZ; l++) {
        float dln = 0.f, un = 0.f, bmn = 0.f, cmn = 0.f;
        if (l < LSZ - 1) {
            dln = drow[(size_t)(l + 1) * DI];
            un  = urow[(size_t)(l + 1) * DI];
            bmn = xd[(size_t)(l + 1) * XPN + DTR + s];
            cmn = xd[(size_t)(l + 1) * XPN + DTR + DS + s];
        }
        float dA = __expf(dl * As);
        h = dA * h + (dl * u) * bm;
        float p = h * cm;
        p += __shfl_xor_sync(0xffffffffu, p, 8);
        p += __shfl_xor_sync(0xffffffffu, p, 4);
        p += __shfl_xor_sync(0xffffffffu, p, 2);
        p += __shfl_xor_sync(0xffffffffu, p, 1);
        if (s == 0) {
            float z = zrow[(size_t)l * (2 * DI)];
            float yv = (p + u * dsk) * (z / (1.f + __expf(-z)));
            yrow[(size_t)l * DI] = yv;
        }
        dl = dln; u = un; bm = bmn; cm = cmn;
    }
}

// ---------------- final: last-token rmsnorm ----------------
__global__ void final_k(const float* __restrict__ resid, const float* __restrict__ nw,
                        const int* __restrict__ mask, float* __restrict__ out) {
    int b = blockIdx.x;
    float ms = 0.f;
    for (int i = threadIdx.x; i < LSZ; i += blockDim.x) ms += (float)mask[b * LSZ + i];
    ms = block_sum(ms);
    int last = (int)(ms + 0.5f) - 1;
    const float* xr = resid + ((size_t)b * LSZ + last) * DM;
    float sacc = 0.f;
    for (int cidx = threadIdx.x; cidx < DM; cidx += blockDim.x) {
        float v = xr[cidx];
        sacc += v * v;
    }
    sacc = block_sum(sacc);
    float inv = rsqrtf(sacc / (float)DM + 1e-5f);
    for (int cidx = threadIdx.x; cidx < DM; cidx += blockDim.x)
        out[b * DM + cidx] = xr[cidx] * inv * nw[cidx];
}

// ---------------- driver ----------------
extern "C" void kernel_launch(void* const* d_in, const int* in_sizes, int n_in,
                              void* d_out, int out_size) {
    const int*   seq       = (const int*)d_in[0];
    const int*   mask      = (const int*)d_in[1];
    const float* emb       = (const float*)d_in[2];
    const float* norm_w    = (const float*)d_in[3];
    const float* in_proj_w = (const float*)d_in[4];
    const float* conv_w    = (const float*)d_in[5];
    const float* conv_b    = (const float*)d_in[6];
    const float* x_proj_w  = (const float*)d_in[7];
    const float* dt_w      = (const float*)d_in[8];
    const float* dt_b      = (const float*)d_in[9];
    const float* A_log     = (const float*)d_in[10];
    const float* D_skip    = (const float*)d_in[11];
    const float* out_w     = (const float*)d_in[12];
    const float* normf_w   = (const float*)d_in[13];

    float *resid, *hn, *xz, *xc, *xdbl, *delta, *y;
    cudaGetSymbolAddress((void**)&resid, g_resid);
    cudaGetSymbolAddress((void**)&hn,    g_hn);
    cudaGetSymbolAddress((void**)&xz,    g_xz);
    cudaGetSymbolAddress((void**)&xc,    g_xc);
    cudaGetSymbolAddress((void**)&xdbl,  g_xdbl);
    cudaGetSymbolAddress((void**)&delta, g_delta);
    cudaGetSymbolAddress((void**)&y,     g_y);

    embed_k<<<(ROWS * (DM / 4) + 255) / 256, 256>>>(seq, emb, resid);

    for (int i = 0; i < NL; i++) {
        rmsnorm_k<<<ROWS, 256>>>(resid, norm_w + i * DM, hn);

        // xz = hn @ in_proj_w^T : (2048x768)(3072x768)^T
        gemm_nt<0><<<dim3((2 * DI) / 64, ROWS / 64), 256>>>(
            hn, in_proj_w + (size_t)i * 2 * DI * DM, xz, nullptr,
            ROWS, 2 * DI, DM, DM);

        conv_silu_k<<<(ROWS * DI) / 256, 256>>>(xz, conv_w + i * DI * 4,
                                                conv_b + i * DI, xc);

        // xdbl = xc @ x_proj_w^T : (2048x1536)(80x1536)^T
        gemm_nt<0><<<dim3((XPN + 63) / 64, ROWS / 64), 256>>>(
            xc, x_proj_w + (size_t)i * XPN * DI, xdbl, nullptr,
            ROWS, XPN, DI, DI);

        // delta = softplus(dt @ dt_w^T + dt_b) : A = xdbl[:, :48] with lda=80
        gemm_nt<1><<<dim3(DI / 64, ROWS / 64), 256>>>(
            xdbl, dt_w + (size_t)i * DI * DTR, delta, dt_b + i * DI,
            ROWS, DI, DTR, XPN);

        scan_k<<<(BSZ * DI / 2 * 32) / 256, 256>>>(
            delta, xc, xdbl, xz, A_log + i * DI * DS, D_skip + i * DI, y);

        // resid += y @ out_w^T : (2048x1536)(768x1536)^T
        gemm_nt<2><<<dim3(DM / 64, ROWS / 64), 256>>>(
            y, out_w + (size_t)i * DM * DI, resid, nullptr,
            ROWS, DM, DI, DI);
    }

    final_k<<<BSZ, 256>>>(resid, normf_w, mask, (float*)d_out);
}

// round 2
// speedup vs baseline: 1.1109x; 1.1109x over previous
#include <cuda_runtime.h>
#include <math.h>

#define BSZ 2
#define LSZ 1024
#define DM 768
#define NL 4
#define DI 1536
#define DS 16
#define DTR 48
#define XPN 80          // DTR + 2*DS
#define ROWS (BSZ*LSZ)  // 2048

// ---------------- scratch (device globals; no allocation allowed) ----------
__device__ float g_resid[ROWS * DM];
__device__ float g_hn[ROWS * DM];
__device__ float g_xz[ROWS * 2 * DI];
__device__ float g_xc[ROWS * DI];
__device__ float g_xdbl[ROWS * XPN];
__device__ float g_delta[ROWS * DI];
__device__ float g_y[ROWS * DI];

// ---------------- f32x2 helpers ----------------
typedef unsigned long long u64;

__device__ __forceinline__ void ffma2(u64& acc, u64 a, u64 b) {
    asm("fma.rn.f32x2 %0, %1, %2, %0;" : "+l"(acc) : "l"(a), "l"(b));
}
__device__ __forceinline__ u64 splat2(float w) {
    u64 r; asm("mov.b64 %0, {%1, %1};" : "=l"(r) : "f"(w)); return r;
}

// ---------------- helpers ----------------
__device__ __forceinline__ float block_sum(float v) {
    __shared__ float sh[8];
    __syncthreads();
#pragma unroll
    for (int o = 16; o; o >>= 1) v += __shfl_xor_sync(0xffffffffu, v, o);
    if ((threadIdx.x & 31) == 0) sh[threadIdx.x >> 5] = v;
    __syncthreads();
    if (threadIdx.x < 32) {
        float t = (threadIdx.x < (blockDim.x >> 5)) ? sh[threadIdx.x] : 0.f;
#pragma unroll
        for (int o = 4; o; o >>= 1) t += __shfl_xor_sync(0xffffffffu, t, o);
        if (threadIdx.x == 0) sh[0] = t;
    }
    __syncthreads();
    return sh[0];
}

// ---------------- embedding gather ----------------
__global__ void embed_k(const int* __restrict__ seq, const float* __restrict__ emb,
                        float* __restrict__ resid) {
    int i = blockIdx.x * blockDim.x + threadIdx.x;
    if (i >= ROWS * (DM / 4)) return;
    int row = i / (DM / 4), c4 = i % (DM / 4);
    int tok = seq[row];
    reinterpret_cast<float4*>(resid)[(size_t)row * (DM / 4) + c4] =
        reinterpret_cast<const float4*>(emb)[(size_t)tok * (DM / 4) + c4];
}

// ---------------- rmsnorm (one block per row) ----------------
__global__ void rmsnorm_k(const float* __restrict__ x, const float* __restrict__ w,
                          float* __restrict__ o) {
    int row = blockIdx.x;
    const float* xr = x + (size_t)row * DM;
    float s = 0.f;
    for (int c = threadIdx.x; c < DM; c += blockDim.x) { float v = xr[c]; s += v * v; }
    s = block_sum(s);
    float inv = rsqrtf(s / (float)DM + 1e-5f);
    for (int c = threadIdx.x; c < DM; c += blockDim.x)
        o[(size_t)row * DM + c] = xr[c] * inv * w[c];
}

// ---------------- depthwise causal conv (width 4) + bias + silu ------------
__global__ void conv_silu_k(const float* __restrict__ xz, const float* __restrict__ cw,
                            const float* __restrict__ cb, float* __restrict__ xc) {
    int i = blockIdx.x * blockDim.x + threadIdx.x;
    if (i >= ROWS * DI) return;
    int d = i % DI;
    int row = i / DI;
    int l = row & (LSZ - 1);
    float acc = cb[d];
#pragma unroll
    for (int k = 0; k < 4; k++) {
        int l2 = l + k - 3;
        if (l2 >= 0)
            acc += xz[(size_t)(row + k - 3) * (2 * DI) + d] * cw[d * 4 + k];
    }
    acc = acc / (1.f + __expf(-acc));
    xc[i] = acc;
}

// ---------------- GEMM: C[m,n] = sum_k A[m,k]*W[n,k], 128x64 tile, f32x2 ---
// Requirements: M % 128 == 0, K % 16 == 0 within each z-chunk.
// EPI: 0 = store, 1 = softplus(acc + bias[n]), 2 = C += acc, 3 = atomicAdd
template <int EPI>
__global__ void __launch_bounds__(256) gemm_f2(
    const float* __restrict__ A, const float* __restrict__ W,
    float* __restrict__ C, const float* __restrict__ bias,
    int M, int N, int K, int lda, int kchunk) {
    __shared__ __align__(16) float As[2][16][128];
    __shared__ __align__(16) float Ws[2][16][64];
    int tid = threadIdx.x;
    int m0 = blockIdx.y * 128, n0 = blockIdx.x * 64;
    int kbeg = blockIdx.z * kchunk;
    int kend = kbeg + kchunk;

    int tm = tid >> 4;           // 0..15 : 8-row strip
    int tn = tid & 15;           // 0..15 : 4-col strip
    int lra = tid >> 1;          // 0..127 A row
    int lka = (tid & 1) * 8;     // 0 or 8
    int lrw = tid >> 2;          // 0..63 W row
    int lkw = (tid & 3) * 4;     // 0,4,8,12

    const float* Arow = A + (size_t)(m0 + lra) * lda + lka;
    bool wvalid = (n0 + lrw) < N;
    const float* Wrow = W + (size_t)(n0 + lrw) * K + lkw;

    float4 apf0, apf1, wpf;
    // prologue load
    apf0 = *reinterpret_cast<const float4*>(Arow + kbeg);
    apf1 = *reinterpret_cast<const float4*>(Arow + kbeg + 4);
    wpf = wvalid ? *reinterpret_cast<const float4*>(Wrow + kbeg)
                 : make_float4(0.f, 0.f, 0.f, 0.f);
    {
        As[0][lka + 0][lra] = apf0.x; As[0][lka + 1][lra] = apf0.y;
        As[0][lka + 2][lra] = apf0.z; As[0][lka + 3][lra] = apf0.w;
        As[0][lka + 4][lra] = apf1.x; As[0][lka + 5][lra] = apf1.y;
        As[0][lka + 6][lra] = apf1.z; As[0][lka + 7][lra] = apf1.w;
        Ws[0][lkw + 0][lrw] = wpf.x; Ws[0][lkw + 1][lrw] = wpf.y;
        Ws[0][lkw + 2][lrw] = wpf.z; Ws[0][lkw + 3][lrw] = wpf.w;
    }
    __syncthreads();

    u64 acc[4][4] = {};
    int cur = 0;
    for (int k0 = kbeg; k0 < kend; k0 += 16) {
        bool nxt = (k0 + 16) < kend;
        if (nxt) {
            apf0 = *reinterpret_cast<const float4*>(Arow + k0 + 16);
            apf1 = *reinterpret_cast<const float4*>(Arow + k0 + 20);
            wpf = wvalid ? *reinterpret_cast<const float4*>(Wrow + k0 + 16)
                         : make_float4(0.f, 0.f, 0.f, 0.f);
        }
#pragma unroll
        for (int kk = 0; kk < 16; kk++) {
            ulonglong2 a01 = *reinterpret_cast<const ulonglong2*>(&As[cur][kk][tm * 8]);
            ulonglong2 a23 = *reinterpret_cast<const ulonglong2*>(&As[cur][kk][tm * 8 + 4]);
            float4 wv = *reinterpret_cast<const float4*>(&Ws[cur][kk][tn * 4]);
            u64 w0 = splat2(wv.x), w1 = splat2(wv.y), w2 = splat2(wv.z), w3 = splat2(wv.w);
            ffma2(acc[0][0], a01.x, w0); ffma2(acc[0][1], a01.x, w1);
            ffma2(acc[0][2], a01.x, w2); ffma2(acc[0][3], a01.x, w3);
            ffma2(acc[1][0], a01.y, w0); ffma2(acc[1][1], a01.y, w1);
            ffma2(acc[1][2], a01.y, w2); ffma2(acc[1][3], a01.y, w3);
            ffma2(acc[2][0], a23.x, w0); ffma2(acc[2][1], a23.x, w1);
            ffma2(acc[2][2], a23.x, w2); ffma2(acc[2][3], a23.x, w3);
            ffma2(acc[3][0], a23.y, w0); ffma2(acc[3][1], a23.y, w1);
            ffma2(acc[3][2], a23.y, w2); ffma2(acc[3][3], a23.y, w3);
        }
        if (nxt) {
            int nb = cur ^ 1;
            As[nb][lka + 0][lra] = apf0.x; As[nb][lka + 1][lra] = apf0.y;
            As[nb][lka + 2][lra] = apf0.z; As[nb][lka + 3][lra] = apf0.w;
            As[nb][lka + 4][lra] = apf1.x; As[nb][lka + 5][lra] = apf1.y;
            As[nb][lka + 6][lra] = apf1.z; As[nb][lka + 7][lra] = apf1.w;
            Ws[nb][lkw + 0][lrw] = wpf.x; Ws[nb][lkw + 1][lrw] = wpf.y;
            Ws[nb][lkw + 2][lrw] = wpf.z; Ws[nb][lkw + 3][lrw] = wpf.w;
            __syncthreads();
            cur = nb;
        }
    }

#pragma unroll
    for (int p = 0; p < 4; p++) {
#pragma unroll
        for (int j = 0; j < 4; j++) {
            int n = n0 + tn * 4 + j;
            if (n >= N) continue;
            float2 f = *reinterpret_cast<float2*>(&acc[p][j]);
            int m = m0 + tm * 8 + p * 2;
#pragma unroll
            for (int h = 0; h < 2; h++) {
                float v = (h == 0) ? f.x : f.y;
                if (EPI == 1) {
                    v += bias[n];
                    v = (v > 20.f) ? v : log1pf(__expf(v));
                }
                size_t idx = (size_t)(m + h) * N + n;
                if (EPI == 2)      C[idx] += v;
                else if (EPI == 3) atomicAdd(&C[idx], v);
                else               C[idx] = v;
            }
        }
    }
}

// ---------------- selective scan: 2 channels per warp ----------------------
__global__ void __launch_bounds__(256) scan_k(
    const float* __restrict__ delta, const float* __restrict__ xc,
    const float* __restrict__ xdbl, const float* __restrict__ xz,
    const float* __restrict__ A_log, const float* __restrict__ dski,
    float* __restrict__ y) {
    int warp = (blockIdx.x * blockDim.x + threadIdx.x) >> 5;
    int lane = threadIdx.x & 31;
    int half = lane >> 4;
    int s = lane & 15;
    int c = warp * 2 + half;
    if (c >= BSZ * DI) return;
    int b = c / DI;
    int d = c % DI;

    float As = -__expf(A_log[d * DS + s]);
    float dsk = dski[d];
    float h = 0.f;
    const float* drow = delta + (size_t)b * LSZ * DI + d;
    const float* urow = xc + (size_t)b * LSZ * DI + d;
    const float* zrow = xz + (size_t)b * LSZ * (2 * DI) + DI + d;
    const float* xd = xdbl + (size_t)b * LSZ * XPN;
    float* yrow = y + (size_t)b * LSZ * DI + d;

    float dl = drow[0];
    float u  = urow[0];
    float bm = xd[DTR + s];
    float cm = xd[DTR + DS + s];
#pragma unroll 4
    for (int l = 0; l < LSZ; l++) {
        float dln = 0.f, un = 0.f, bmn = 0.f, cmn = 0.f;
        if (l < LSZ - 1) {
            dln = drow[(size_t)(l + 1) * DI];
            un  = urow[(size_t)(l + 1) * DI];
            bmn = xd[(size_t)(l + 1) * XPN + DTR + s];
            cmn = xd[(size_t)(l + 1) * XPN + DTR + DS + s];
        }
        float dA = __expf(dl * As);
        h = dA * h + (dl * u) * bm;
        float p = h * cm;
        p += __shfl_xor_sync(0xffffffffu, p, 8);
        p += __shfl_xor_sync(0xffffffffu, p, 4);
        p += __shfl_xor_sync(0xffffffffu, p, 2);
        p += __shfl_xor_sync(0xffffffffu, p, 1);
        if (s == 0) {
            float z = zrow[(size_t)l * (2 * DI)];
            float yv = (p + u * dsk) * (z / (1.f + __expf(-z)));
            yrow[(size_t)l * DI] = yv;
        }
        dl = dln; u = un; bm = bmn; cm = cmn;
    }
}

// ---------------- final: last-token rmsnorm ----------------
__global__ void final_k(const float* __restrict__ resid, const float* __restrict__ nw,
                        const int* __restrict__ mask, float* __restrict__ out) {
    int b = blockIdx.x;
    float ms = 0.f;
    for (int i = threadIdx.x; i < LSZ; i += blockDim.x) ms += (float)mask[b * LSZ + i];
    ms = block_sum(ms);
    int last = (int)(ms + 0.5f) - 1;
    const float* xr = resid + ((size_t)b * LSZ + last) * DM;
    float sacc = 0.f;
    for (int cidx = threadIdx.x; cidx < DM; cidx += blockDim.x) {
        float v = xr[cidx];
        sacc += v * v;
    }
    sacc = block_sum(sacc);
    float inv = rsqrtf(sacc / (float)DM + 1e-5f);
    for (int cidx = threadIdx.x; cidx < DM; cidx += blockDim.x)
        out[b * DM + cidx] = xr[cidx] * inv * nw[cidx];
}

// ---------------- driver ----------------
extern "C" void kernel_launch(void* const* d_in, const int* in_sizes, int n_in,
                              void* d_out, int out_size) {
    const int*   seq       = (const int*)d_in[0];
    const int*   mask      = (const int*)d_in[1];
    const float* emb       = (const float*)d_in[2];
    const float* norm_w    = (const float*)d_in[3];
    const float* in_proj_w = (const float*)d_in[4];
    const float* conv_w    = (const float*)d_in[5];
    const float* conv_b    = (const float*)d_in[6];
    const float* x_proj_w  = (const float*)d_in[7];
    const float* dt_w      = (const float*)d_in[8];
    const float* dt_b      = (const float*)d_in[9];
    const float* A_log     = (const float*)d_in[10];
    const float* D_skip    = (const float*)d_in[11];
    const float* out_w     = (const float*)d_in[12];
    const float* normf_w   = (const float*)d_in[13];

    float *resid, *hn, *xz, *xc, *xdbl, *delta, *y;
    cudaGetSymbolAddress((void**)&resid, g_resid);
    cudaGetSymbolAddress((void**)&hn,    g_hn);
    cudaGetSymbolAddress((void**)&xz,    g_xz);
    cudaGetSymbolAddress((void**)&xc,    g_xc);
    cudaGetSymbolAddress((void**)&xdbl,  g_xdbl);
    cudaGetSymbolAddress((void**)&delta, g_delta);
    cudaGetSymbolAddress((void**)&y,     g_y);

    embed_k<<<(ROWS * (DM / 4) + 255) / 256, 256>>>(seq, emb, resid);

    for (int i = 0; i < NL; i++) {
        rmsnorm_k<<<ROWS, 256>>>(resid, norm_w + i * DM, hn);

        // xz = hn @ in_proj_w^T : (2048x768)(3072x768)^T
        gemm_f2<0><<<dim3((2 * DI) / 64, ROWS / 128, 1), 256>>>(
            hn, in_proj_w + (size_t)i * 2 * DI * DM, xz, nullptr,
            ROWS, 2 * DI, DM, DM, DM);

        conv_silu_k<<<(ROWS * DI) / 256, 256>>>(xz, conv_w + i * DI * 4,
                                                conv_b + i * DI, xc);

        // xdbl = xc @ x_proj_w^T : (2048x1536)(80x1536)^T, split-K z=6
        cudaMemsetAsync(xdbl, 0, (size_t)ROWS * XPN * sizeof(float));
        gemm_f2<3><<<dim3((XPN + 63) / 64, ROWS / 128, 6), 256>>>(
            xc, x_proj_w + (size_t)i * XPN * DI, xdbl, nullptr,
            ROWS, XPN, DI, DI, DI / 6);

        // delta = softplus(xdbl[:, :48] @ dt_w^T + dt_b)
        gemm_f2<1><<<dim3(DI / 64, ROWS / 128, 1), 256>>>(
            xdbl, dt_w + (size_t)i * DI * DTR, delta, dt_b + i * DI,
            ROWS, DI, DTR, XPN, DTR);

        scan_k<<<(BSZ * DI / 2 * 32) / 256, 256>>>(
            delta, xc, xdbl, xz, A_log + i * DI * DS, D_skip + i * DI, y);

        // resid += y @ out_w^T : (2048x1536)(768x1536)^T
        gemm_f2<2><<<dim3(DM / 64, ROWS / 128, 1), 256>>>(
            y, out_w + (size_t)i * DM * DI, resid, nullptr,
            ROWS, DM, DI, DI, DI);
    }

    final_k<<<BSZ, 256>>>(resid, normf_w, mask, (float*)d_out);
}

// round 4
// speedup vs baseline: 1.3703x; 1.2335x over previous
#include <cuda_runtime.h>
#include <cuda_bf16.h>
#include <math.h>
#include <stdint.h>

#define BSZ 2
#define LSZ 1024
#define DM 768
#define NL 4
#define DI 1536
#define DS 16
#define DTR 48
#define XPN 80          // DTR + 2*DS
#define ROWS (BSZ*LSZ)  // 2048

// extended-K sizes (3 segments for bf16-split exact GEMM)
#define KE_IN   (3*DM)     // 2304
#define KE_BIG  (3*DI)     // 4608
#define KE_DT   (3*64)     // 192

// ---------------- scratch (device globals; no allocation allowed) ----------
__device__ float g_resid[ROWS * DM];
__device__ float g_xz[ROWS * 2 * DI];
__device__ float g_xc[ROWS * DI];
__device__ float g_xdbl[ROWS * XPN];
__device__ float g_delta[ROWS * DI];
__device__ __nv_bfloat16 g_aext[ROWS * KE_BIG];        // activation ext (reused)
__device__ __nv_bfloat16 g_wext[(2 * DI) * KE_IN];     // weight ext (max 3072x2304)

// ---------------- small helpers ----------------
__device__ __forceinline__ uint32_t smem_to_u32(const void* p) {
    uint32_t a;
    asm("{ .reg .u64 t; cvta.to.shared.u64 t, %1; cvt.u32.u64 %0, t; }"
        : "=r"(a) : "l"(p));
    return a;
}
__device__ __forceinline__ void cp16(uint32_t dst, const void* src) {
    asm volatile("cp.async.cg.shared.global [%0], [%1], 16;" :: "r"(dst), "l"(src));
}
__device__ __forceinline__ void ldsm4(uint32_t* r, uint32_t addr) {
    asm volatile("ldmatrix.sync.aligned.m8n8.x4.shared.b16 {%0,%1,%2,%3}, [%4];"
        : "=r"(r[0]), "=r"(r[1]), "=r"(r[2]), "=r"(r[3]) : "r"(addr));
}
__device__ __forceinline__ void mma16816(float* c, const uint32_t* a, const uint32_t* b) {
    asm volatile("mma.sync.aligned.m16n8k16.row.col.f32.bf16.bf16.f32 "
        "{%0,%1,%2,%3}, {%4,%5,%6,%7}, {%8,%9}, {%0,%1,%2,%3};"
        : "+f"(c[0]), "+f"(c[1]), "+f"(c[2]), "+f"(c[3])
        : "r"(a[0]), "r"(a[1]), "r"(a[2]), "r"(a[3]), "r"(b[0]), "r"(b[1]));
}
__device__ __forceinline__ void bsplit(float v, __nv_bfloat16& h, __nv_bfloat16& l) {
    h = __float2bfloat16(v);
    l = __float2bfloat16(v - __bfloat162float(h));
}

__device__ __forceinline__ float block_sum(float v) {
    __shared__ float sh[8];
    __syncthreads();
#pragma unroll
    for (int o = 16; o; o >>= 1) v += __shfl_xor_sync(0xffffffffu, v, o);
    if ((threadIdx.x & 31) == 0) sh[threadIdx.x >> 5] = v;
    __syncthreads();
    if (threadIdx.x < 32) {
        float t = (threadIdx.x < (blockDim.x >> 5)) ? sh[threadIdx.x] : 0.f;
#pragma unroll
        for (int o = 4; o; o >>= 1) t += __shfl_xor_sync(0xffffffffu, t, o);
        if (threadIdx.x == 0) sh[0] = t;
    }
    __syncthreads();
    return sh[0];
}

// ---------------- embedding gather ----------------
__global__ void embed_k(const int* __restrict__ seq, const float* __restrict__ emb,
                        float* __restrict__ resid) {
    int i = blockIdx.x * blockDim.x + threadIdx.x;
    if (i >= ROWS * (DM / 4)) return;
    int row = i / (DM / 4), c4 = i % (DM / 4);
    int tok = seq[row];
    reinterpret_cast<float4*>(resid)[(size_t)row * (DM / 4) + c4] =
        reinterpret_cast<const float4*>(emb)[(size_t)tok * (DM / 4) + c4];
}

// ---------------- rmsnorm: writes ext layout (Kext=2304) -------------------
__global__ void rmsnorm_k(const float* __restrict__ x, const float* __restrict__ w,
                          __nv_bfloat16* __restrict__ ae) {
    int row = blockIdx.x;
    const float* xr = x + (size_t)row * DM;
    float s = 0.f;
    for (int c = threadIdx.x; c < DM; c += blockDim.x) { float v = xr[c]; s += v * v; }
    s = block_sum(s);
    float inv = rsqrtf(s / (float)DM + 1e-5f);
    __nv_bfloat16* ar = ae + (size_t)row * KE_IN;
    for (int c = threadIdx.x; c < DM; c += blockDim.x) {
        float v = xr[c] * inv * w[c];
        __nv_bfloat16 h, l; bsplit(v, h, l);
        ar[c] = h; ar[c + DM] = h; ar[c + 2 * DM] = l;
    }
}

// ---------------- weight prep: fp32 [N,Ksrc] -> ext bf16 [Npad, 3*Kpad] ----
// segments: Wh | Wl | Wh  (pairs with A's Ah | Ah | Al)
__global__ void wprep_k(const float* __restrict__ w, __nv_bfloat16* __restrict__ e,
                        int N, int Npad, int Ksrc, int Kpad) {
    int i = blockIdx.x * blockDim.x + threadIdx.x;
    if (i >= Npad * Kpad) return;
    int n = i / Kpad, k = i - n * Kpad;
    float v = (n < N && k < Ksrc) ? w[(size_t)n * Ksrc + k] : 0.f;
    __nv_bfloat16 h, l; bsplit(v, h, l);
    __nv_bfloat16* er = e + (size_t)n * (3 * Kpad);
    er[k] = h; er[k + Kpad] = l; er[k + 2 * Kpad] = h;
}

// ---------------- dt A prep: xdbl[:, :48] -> ext [ROWS, 192] ---------------
__global__ void dtprep_k(const float* __restrict__ xdbl, __nv_bfloat16* __restrict__ ae) {
    int i = blockIdx.x * blockDim.x + threadIdx.x;
    if (i >= ROWS * 64) return;
    int r = i >> 6, k = i & 63;
    float v = (k < DTR) ? xdbl[(size_t)r * XPN + k] : 0.f;
    __nv_bfloat16 h, l; bsplit(v, h, l);
    __nv_bfloat16* ar = ae + (size_t)r * KE_DT;
    ar[k] = h; ar[k + 64] = h; ar[k + 128] = l;
}

// ---------------- depthwise conv + silu: fp32 + ext (Kext=4608) ------------
__global__ void conv_silu_k(const float* __restrict__ xz, const float* __restrict__ cw,
                            const float* __restrict__ cb, float* __restrict__ xc,
                            __nv_bfloat16* __restrict__ ae) {
    int i = blockIdx.x * blockDim.x + threadIdx.x;
    if (i >= ROWS * DI) return;
    int d = i % DI;
    int row = i / DI;
    int l = row & (LSZ - 1);
    float acc = cb[d];
#pragma unroll
    for (int k = 0; k < 4; k++) {
        int l2 = l + k - 3;
        if (l2 >= 0)
            acc += xz[(size_t)(row + k - 3) * (2 * DI) + d] * cw[d * 4 + k];
    }
    acc = acc / (1.f + __expf(-acc));
    xc[i] = acc;
    __nv_bfloat16 h, lo; bsplit(acc, h, lo);
    __nv_bfloat16* ar = ae + (size_t)row * KE_BIG;
    ar[d] = h; ar[d + DI] = h; ar[d + 2 * DI] = lo;
}

// ---------------- bf16 tensor-core GEMM: C = Aext @ Wext^T -----------------
// CTA tile 128x128x32, 8 warps (4x2), double-buffered cp.async.
// EPI: 0 = store, 1 = softplus(acc + bias[n]), 3 = atomicAdd (guard n < N)
template <int EPI>
__global__ void __launch_bounds__(256) gemm_bf(
    const __nv_bfloat16* __restrict__ Aext, const __nv_bfloat16* __restrict__ Wext,
    float* __restrict__ C, const float* __restrict__ bias,
    int Kext, int kIters, int N, int ldc) {
    __shared__ __align__(16) uint8_t sA[2][8192];
    __shared__ __align__(16) uint8_t sB[2][8192];
    int tid = threadIdx.x;
    int wid = tid >> 5, lane = tid & 31;
    int m0 = blockIdx.y * 128, n0 = blockIdx.x * 128;
    int kbase = blockIdx.z * kIters * 32;

    int warp_m = wid & 3, warp_n = wid >> 2;   // 4 x 2 warp grid

    // global load mapping: thread -> (row, 16B chunk)
    int lrow = tid >> 2;       // 0..63
    int lch = tid & 3;         // 0..3
    const char* Ag = (const char*)(Aext + (size_t)(m0 + lrow) * Kext + kbase + lch * 8);
    const char* Bg = (const char*)(Wext + (size_t)(n0 + lrow) * Kext + kbase + lch * 8);
    size_t rstep = (size_t)64 * Kext * 2;  // bytes for +64 rows
    uint32_t sAu = smem_to_u32(sA), sBu = smem_to_u32(sB);
    uint32_t dst0 = (uint32_t)(lrow * 64 + ((lch ^ ((lrow >> 1) & 3)) * 16));

    float acc[2][8][4];
#pragma unroll
    for (int a = 0; a < 2; a++)
#pragma unroll
        for (int b = 0; b < 8; b++)
#pragma unroll
            for (int c = 0; c < 4; c++) acc[a][b][c] = 0.f;

#define LOAD_STAGE(st, kt) do { \
    uint32_t _o = (uint32_t)(st) * 8192 + dst0; \
    size_t _g = (size_t)(kt) * 64; \
    cp16(sAu + _o, Ag + _g); \
    cp16(sAu + _o + 4096, Ag + rstep + _g); \
    cp16(sBu + _o, Bg + _g); \
    cp16(sBu + _o + 4096, Bg + rstep + _g); \
    asm volatile("cp.async.commit_group;"); \
} while (0)

    LOAD_STAGE(0, 0);

    for (int kt = 0; kt < kIters; kt++) {
        asm volatile("cp.async.wait_group 0;" ::: "memory");
        __syncthreads();
        if (kt + 1 < kIters) LOAD_STAGE((kt + 1) & 1, kt + 1);
        uint32_t baseA = sAu + (kt & 1) * 8192;
        uint32_t baseB = sBu + (kt & 1) * 8192;
#pragma unroll
        for (int ks = 0; ks < 2; ks++) {
            int lr16 = lane & 15;
            int ach = ks * 2 + (lane >> 4);
            uint32_t afr[2][4];
#pragma unroll
            for (int mf = 0; mf < 2; mf++) {
                int r = warp_m * 32 + mf * 16 + lr16;
                ldsm4(afr[mf], baseA + r * 64 + ((ach ^ ((r >> 1) & 3)) * 16));
            }
#pragma unroll
            for (int np = 0; np < 4; np++) {
                int r = warp_n * 64 + np * 16 + lr16;
                uint32_t bfr[4];
                ldsm4(bfr, baseB + r * 64 + ((ach ^ ((r >> 1) & 3)) * 16));
                uint32_t b0[2] = {bfr[0], bfr[2]};
                uint32_t b1[2] = {bfr[1], bfr[3]};
#pragma unroll
                for (int mf = 0; mf < 2; mf++) {
                    mma16816(acc[mf][np * 2], afr[mf], b0);
                    mma16816(acc[mf][np * 2 + 1], afr[mf], b1);
                }
            }
        }
    }

    // epilogue
    int trow = lane >> 2, tc2 = (lane & 3) * 2;
#pragma unroll
    for (int mf = 0; mf < 2; mf++) {
#pragma unroll
        for (int nf = 0; nf < 8; nf++) {
            int n = n0 + warp_n * 64 + nf * 8 + tc2;
            int m = m0 + warp_m * 32 + mf * 16 + trow;
#pragma unroll
            for (int hh = 0; hh < 2; hh++) {     // hh=0 -> row m, hh=1 -> row m+8
                float v0 = acc[mf][nf][hh * 2];
                float v1 = acc[mf][nf][hh * 2 + 1];
                int mr = m + hh * 8;
                if (EPI == 1) {
                    v0 += bias[n];     v0 = (v0 > 20.f) ? v0 : log1pf(__expf(v0));
                    v1 += bias[n + 1]; v1 = (v1 > 20.f) ? v1 : log1pf(__expf(v1));
                }
                if (EPI == 3) {
                    if (n < N)     atomicAdd(&C[(size_t)mr * ldc + n], v0);
                    if (n + 1 < N) atomicAdd(&C[(size_t)mr * ldc + n + 1], v1);
                } else {
                    *reinterpret_cast<float2*>(&C[(size_t)mr * ldc + n]) =
                        make_float2(v0, v1);
                }
            }
        }
    }
#undef LOAD_STAGE
}

// ---------------- selective scan: 2 channels/warp, writes ext y ------------
__global__ void __launch_bounds__(256) scan_k(
    const float* __restrict__ delta, const float* __restrict__ xc,
    const float* __restrict__ xdbl, const float* __restrict__ xz,
    const float* __restrict__ A_log, const float* __restrict__ dski,
    __nv_bfloat16* __restrict__ ye) {
    int warp = (blockIdx.x * blockDim.x + threadIdx.x) >> 5;
    int lane = threadIdx.x & 31;
    int half = lane >> 4;
    int s = lane & 15;
    int c = warp * 2 + half;
    if (c >= BSZ * DI) return;
    int b = c / DI;
    int d = c % DI;

    float As = -__expf(A_log[d * DS + s]);
    float dsk = dski[d];
    float h = 0.f;
    const float* drow = delta + (size_t)b * LSZ * DI + d;
    const float* urow = xc + (size_t)b * LSZ * DI + d;
    const float* zrow = xz + (size_t)b * LSZ * (2 * DI) + DI + d;
    const float* xd = xdbl + (size_t)b * LSZ * XPN;
    __nv_bfloat16* yr = ye + (size_t)b * LSZ * KE_BIG + d;

    float dl = drow[0];
    float u  = urow[0];
    float bm = xd[DTR + s];
    float cm = xd[DTR + DS + s];
#pragma unroll 4
    for (int l = 0; l < LSZ; l++) {
        float dln = 0.f, un = 0.f, bmn = 0.f, cmn = 0.f;
        if (l < LSZ - 1) {
            dln = drow[(size_t)(l + 1) * DI];
            un  = urow[(size_t)(l + 1) * DI];
            bmn = xd[(size_t)(l + 1) * XPN + DTR + s];
            cmn = xd[(size_t)(l + 1) * XPN + DTR + DS + s];
        }
        float dA = __expf(dl * As);
        h = dA * h + (dl * u) * bm;
        float p = h * cm;
        p += __shfl_xor_sync(0xffffffffu, p, 8);
        p += __shfl_xor_sync(0xffffffffu, p, 4);
        p += __shfl_xor_sync(0xffffffffu, p, 2);
        p += __shfl_xor_sync(0xffffffffu, p, 1);
        if (s == 0) {
            float z = zrow[(size_t)l * (2 * DI)];
            float yv = (p + u * dsk) * (z / (1.f + __expf(-z)));
            __nv_bfloat16 hh, ll; bsplit(yv, hh, ll);
            __nv_bfloat16* yp = yr + (size_t)l * KE_BIG;
            yp[0] = hh; yp[DI] = hh; yp[2 * DI] = ll;
        }
        dl = dln; u = un; bm = bmn; cm = cmn;
    }
}

// ---------------- final: last-token rmsnorm ----------------
__global__ void final_k(const float* __restrict__ resid, const float* __restrict__ nw,
                        const int* __restrict__ mask, float* __restrict__ out) {
    int b = blockIdx.x;
    float ms = 0.f;
    for (int i = threadIdx.x; i < LSZ; i += blockDim.x) ms += (float)mask[b * LSZ + i];
    ms = block_sum(ms);
    int last = (int)(ms + 0.5f) - 1;
    const float* xr = resid + ((size_t)b * LSZ + last) * DM;
    float sacc = 0.f;
    for (int cidx = threadIdx.x; cidx < DM; cidx += blockDim.x) {
        float v = xr[cidx];
        sacc += v * v;
    }
    sacc = block_sum(sacc);
    float inv = rsqrtf(sacc / (float)DM + 1e-5f);
    for (int cidx = threadIdx.x; cidx < DM; cidx += blockDim.x)
        out[b * DM + cidx] = xr[cidx] * inv * nw[cidx];
}

// ---------------- driver ----------------
extern "C" void kernel_launch(void* const* d_in, const int* in_sizes, int n_in,
                              void* d_out, int out_size) {
    const int*   seq       = (const int*)d_in[0];
    const int*   mask      = (const int*)d_in[1];
    const float* emb       = (const float*)d_in[2];
    const float* norm_w    = (const float*)d_in[3];
    const float* in_proj_w = (const float*)d_in[4];
    const float* conv_w    = (const float*)d_in[5];
    const float* conv_b    = (const float*)d_in[6];
    const float* x_proj_w  = (const float*)d_in[7];
    const float* dt_w      = (const float*)d_in[8];
    const float* dt_b      = (const float*)d_in[9];
    const float* A_log     = (const float*)d_in[10];
    const float* D_skip    = (const float*)d_in[11];
    const float* out_w     = (const float*)d_in[12];
    const float* normf_w   = (const float*)d_in[13];

    float *resid, *xz, *xc, *xdbl, *delta;
    __nv_bfloat16 *ae, *we;
    cudaGetSymbolAddress((void**)&resid, g_resid);
    cudaGetSymbolAddress((void**)&xz,    g_xz);
    cudaGetSymbolAddress((void**)&xc,    g_xc);
    cudaGetSymbolAddress((void**)&xdbl,  g_xdbl);
    cudaGetSymbolAddress((void**)&delta, g_delta);
    cudaGetSymbolAddress((void**)&ae,    g_aext);
    cudaGetSymbolAddress((void**)&we,    g_wext);

    embed_k<<<(ROWS * (DM / 4) + 255) / 256, 256>>>(seq, emb, resid);

    for (int i = 0; i < NL; i++) {
        // hn ext = rmsnorm(resid)
        rmsnorm_k<<<ROWS, 256>>>(resid, norm_w + i * DM, ae);
        // in_proj: xz = hn @ W^T   (N=3072, K=768, Kext=2304, 72 iters)
        wprep_k<<<(2 * DI * DM + 255) / 256, 256>>>(
            in_proj_w + (size_t)i * 2 * DI * DM, we, 2 * DI, 2 * DI, DM, DM);
        gemm_bf<0><<<dim3(24, 16, 1), 256>>>(
            ae, we, xz, nullptr, KE_IN, KE_IN / 32, 2 * DI, 2 * DI);

        // conv + silu -> xc fp32 + ae ext (Kext=4608)
        conv_silu_k<<<(ROWS * DI) / 256, 256>>>(
            xz, conv_w + i * DI * 4, conv_b + i * DI, xc, ae);

        // x_proj: xdbl = xc @ W^T  (N=80 pad 128, Kext=4608, split-K z=8)
        wprep_k<<<(128 * DI + 255) / 256, 256>>>(
            x_proj_w + (size_t)i * XPN * DI, we, XPN, 128, DI, DI);
        cudaMemsetAsync(xdbl, 0, (size_t)ROWS * XPN * sizeof(float));
        gemm_bf<3><<<dim3(1, 16, 8), 256>>>(
            ae, we, xdbl, nullptr, KE_BIG, KE_BIG / (8 * 32), XPN, XPN);

        // dt: delta = softplus(xdbl[:, :48] @ dt_w^T + dt_b)  (Kpad=64)
        wprep_k<<<(DI * 64 + 255) / 256, 256>>>(
            dt_w + (size_t)i * DI * DTR, we, DI, DI, DTR, 64);
        dtprep_k<<<(ROWS * 64 + 255) / 256, 256>>>(xdbl, ae);
        gemm_bf<1><<<dim3(12, 16, 1), 256>>>(
            ae, we, delta, dt_b + i * DI, KE_DT, KE_DT / 32, DI, DI);

        // selective scan -> y ext (Kext=4608)
        scan_k<<<(BSZ * DI / 2 * 32) / 256, 256>>>(
            delta, xc, xdbl, xz, A_log + i * DI * DS, D_skip + i * DI, ae);

        // out_proj: resid += y @ W^T  (N=768, Kext=4608, split-K z=2, atomics)
        wprep_k<<<(DM * DI + 255) / 256, 256>>>(
            out_w + (size_t)i * DM * DI, we, DM, DM, DI, DI);
        gemm_bf<3><<<dim3(6, 16, 2), 256>>>(
            ae, we, resid, nullptr, KE_BIG, KE_BIG / (2 * 32), DM, DM);
    }

    final_k<<<BSZ, 256>>>(resid, normf_w, mask, (float*)d_out);
}

// round 5
// speedup vs baseline: 1.9395x; 1.4154x over previous
#include <cuda_runtime.h>
#include <cuda_bf16.h>
#include <math.h>
#include <stdint.h>

#define BSZ 2
#define LSZ 1024
#define DM 768
#define NL 4
#define DI 1536
#define DS 16
#define DTR 48
#define XPN 80          // DTR + 2*DS
#define ROWS (BSZ*LSZ)  // 2048

// extended-K sizes (3 segments for bf16-split exact GEMM)
#define KE_IN   (3*DM)     // 2304
#define KE_BIG  (3*DI)     // 4608
#define KE_DT   (3*64)     // 192

#define STAGES 4
#define GSMEM (STAGES*16384)   // 64KB dynamic smem

// ---------------- scratch (device globals; no allocation allowed) ----------
__device__ float g_resid[ROWS * DM];
__device__ float g_xz[ROWS * 2 * DI];
__device__ float g_xc[ROWS * DI];
__device__ float g_xdbl[ROWS * XPN];
__device__ float g_delta[ROWS * DI];
__device__ __nv_bfloat16 g_aext[ROWS * KE_BIG];          // activation ext (reused)
__device__ __nv_bfloat16 g_wi[NL][(2 * DI) * KE_IN];     // in_proj ext
__device__ __nv_bfloat16 g_wo[NL][DM * KE_BIG];          // out_proj ext
__device__ __nv_bfloat16 g_wx[NL][128 * KE_BIG];         // x_proj ext (N padded 128)
__device__ __nv_bfloat16 g_wd[NL][DI * KE_DT];           // dt ext

// ---------------- small helpers ----------------
__device__ __forceinline__ uint32_t smem_to_u32(const void* p) {
    uint32_t a;
    asm("{ .reg .u64 t; cvta.to.shared.u64 t, %1; cvt.u32.u64 %0, t; }"
        : "=r"(a) : "l"(p));
    return a;
}
__device__ __forceinline__ void cp16(uint32_t dst, const void* src) {
    asm volatile("cp.async.cg.shared.global [%0], [%1], 16;" :: "r"(dst), "l"(src));
}
__device__ __forceinline__ void ldsm4(uint32_t* r, uint32_t addr) {
    asm volatile("ldmatrix.sync.aligned.m8n8.x4.shared.b16 {%0,%1,%2,%3}, [%4];"
        : "=r"(r[0]), "=r"(r[1]), "=r"(r[2]), "=r"(r[3]) : "r"(addr));
}
__device__ __forceinline__ void mma16816(float* c, const uint32_t* a, const uint32_t* b) {
    asm volatile("mma.sync.aligned.m16n8k16.row.col.f32.bf16.bf16.f32 "
        "{%0,%1,%2,%3}, {%4,%5,%6,%7}, {%8,%9}, {%0,%1,%2,%3};"
        : "+f"(c[0]), "+f"(c[1]), "+f"(c[2]), "+f"(c[3])
        : "r"(a[0]), "r"(a[1]), "r"(a[2]), "r"(a[3]), "r"(b[0]), "r"(b[1]));
}
__device__ __forceinline__ void bsplit(float v, __nv_bfloat16& h, __nv_bfloat16& l) {
    h = __float2bfloat16(v);
    l = __float2bfloat16(v - __bfloat162float(h));
}
__device__ __forceinline__ float softplus_f(float v) {
    return fmaxf(v, 0.f) + __logf(1.f + __expf(-fabsf(v)));
}

__device__ __forceinline__ float block_sum(float v) {
    __shared__ float sh[8];
    __syncthreads();
#pragma unroll
    for (int o = 16; o; o >>= 1) v += __shfl_xor_sync(0xffffffffu, v, o);
    if ((threadIdx.x & 31) == 0) sh[threadIdx.x >> 5] = v;
    __syncthreads();
    if (threadIdx.x < 32) {
        float t = (threadIdx.x < (blockDim.x >> 5)) ? sh[threadIdx.x] : 0.f;
#pragma unroll
        for (int o = 4; o; o >>= 1) t += __shfl_xor_sync(0xffffffffu, t, o);
        if (threadIdx.x == 0) sh[0] = t;
    }
    __syncthreads();
    return sh[0];
}

// ---------------- embedding gather ----------------
__global__ void embed_k(const int* __restrict__ seq, const float* __restrict__ emb,
                        float* __restrict__ resid) {
    int i = blockIdx.x * blockDim.x + threadIdx.x;
    if (i >= ROWS * (DM / 4)) return;
    int row = i / (DM / 4), c4 = i % (DM / 4);
    int tok = seq[row];
    reinterpret_cast<float4*>(resid)[(size_t)row * (DM / 4) + c4] =
        reinterpret_cast<const float4*>(emb)[(size_t)tok * (DM / 4) + c4];
}

// ---------------- rmsnorm: writes ext layout (Kext=2304) -------------------
__global__ void rmsnorm_k(const float* __restrict__ x, const float* __restrict__ w,
                          __nv_bfloat16* __restrict__ ae) {
    int row = blockIdx.x;
    const float* xr = x + (size_t)row * DM;
    float s = 0.f;
    for (int c = threadIdx.x; c < DM; c += blockDim.x) { float v = xr[c]; s += v * v; }
    s = block_sum(s);
    float inv = rsqrtf(s / (float)DM + 1e-5f);
    __nv_bfloat16* ar = ae + (size_t)row * KE_IN;
    for (int c = threadIdx.x; c < DM; c += blockDim.x) {
        float v = xr[c] * inv * w[c];
        __nv_bfloat16 h, l; bsplit(v, h, l);
        ar[c] = h; ar[c + DM] = h; ar[c + 2 * DM] = l;
    }
}

// ---------------- weight prep: fp32 [N,Ksrc] -> ext bf16 [Npad, 3*Kpad] ----
// segments: Wh | Wl | Wh  (pairs with A's Ah | Ah | Al)
__global__ void wprep_k(const float* __restrict__ w, __nv_bfloat16* __restrict__ e,
                        int N, int Npad, int Ksrc, int Kpad) {
    int i = blockIdx.x * blockDim.x + threadIdx.x;
    if (i >= Npad * Kpad) return;
    int n = i / Kpad, k = i - n * Kpad;
    float v = (n < N && k < Ksrc) ? w[(size_t)n * Ksrc + k] : 0.f;
    __nv_bfloat16 h, l; bsplit(v, h, l);
    __nv_bfloat16* er = e + (size_t)n * (3 * Kpad);
    er[k] = h; er[k + Kpad] = l; er[k + 2 * Kpad] = h;
}

// ---------------- dt A prep: xdbl[:, :48] -> ext [ROWS, 192] ---------------
__global__ void dtprep_k(const float* __restrict__ xdbl, __nv_bfloat16* __restrict__ ae) {
    int i = blockIdx.x * blockDim.x + threadIdx.x;
    if (i >= ROWS * 64) return;
    int r = i >> 6, k = i & 63;
    float v = (k < DTR) ? xdbl[(size_t)r * XPN + k] : 0.f;
    __nv_bfloat16 h, l; bsplit(v, h, l);
    __nv_bfloat16* ar = ae + (size_t)r * KE_DT;
    ar[k] = h; ar[k + 64] = h; ar[k + 128] = l;
}

// ---------------- depthwise conv + silu: fp32 + ext (Kext=4608) ------------
__global__ void conv_silu_k(const float* __restrict__ xz, const float* __restrict__ cw,
                            const float* __restrict__ cb, float* __restrict__ xc,
                            __nv_bfloat16* __restrict__ ae) {
    int i = blockIdx.x * blockDim.x + threadIdx.x;
    if (i >= ROWS * DI) return;
    int d = i % DI;
    int row = i / DI;
    int l = row & (LSZ - 1);
    float acc = cb[d];
#pragma unroll
    for (int k = 0; k < 4; k++) {
        int l2 = l + k - 3;
        if (l2 >= 0)
            acc += xz[(size_t)(row + k - 3) * (2 * DI) + d] * cw[d * 4 + k];
    }
    acc = acc / (1.f + __expf(-acc));
    xc[i] = acc;
    __nv_bfloat16 h, lo; bsplit(acc, h, lo);
    __nv_bfloat16* ar = ae + (size_t)row * KE_BIG;
    ar[d] = h; ar[d + DI] = h; ar[d + 2 * DI] = lo;
}

// ---------------- bf16 tensor-core GEMM: C = Aext @ Wext^T -----------------
// CTA tile 128x128x32, 8 warps (4x2), 4-stage cp.async pipeline.
// EPI: 0 = store, 1 = softplus(acc + bias[n]), 3 = atomicAdd (guard n < N)
template <int EPI>
__global__ void __launch_bounds__(256) gemm_bf(
    const __nv_bfloat16* __restrict__ Aext, const __nv_bfloat16* __restrict__ Wext,
    float* __restrict__ C, const float* __restrict__ bias,
    int Kext, int kIters, int N, int ldc) {
    extern __shared__ __align__(16) uint8_t smem[];
    int tid = threadIdx.x;
    int wid = tid >> 5, lane = tid & 31;
    int m0 = blockIdx.y * 128, n0 = blockIdx.x * 128;
    int kbase = blockIdx.z * kIters * 32;

    int warp_m = wid & 3, warp_n = wid >> 2;   // 4 x 2 warp grid

    int lrow = tid >> 2;       // 0..63
    int lch = tid & 3;         // 0..3
    const char* Ag = (const char*)(Aext + (size_t)(m0 + lrow) * Kext + kbase + lch * 8);
    const char* Bg = (const char*)(Wext + (size_t)(n0 + lrow) * Kext + kbase + lch * 8);
    size_t rstep = (size_t)64 * Kext * 2;  // bytes for +64 rows
    uint32_t su = smem_to_u32(smem);
    uint32_t dst0 = (uint32_t)(lrow * 64 + ((lch ^ ((lrow >> 1) & 3)) * 16));

    float acc[2][8][4];
#pragma unroll
    for (int a = 0; a < 2; a++)
#pragma unroll
        for (int b = 0; b < 8; b++)
#pragma unroll
            for (int c = 0; c < 4; c++) acc[a][b][c] = 0.f;

#define LOAD_STAGE(st, kt) do { \
    if ((kt) < kIters) { \
        uint32_t _o = (uint32_t)(st) * 16384 + dst0; \
        size_t _g = (size_t)(kt) * 64; \
        cp16(su + _o, Ag + _g); \
        cp16(su + _o + 4096, Ag + rstep + _g); \
        cp16(su + _o + 8192, Bg + _g); \
        cp16(su + _o + 12288, Bg + rstep + _g); \
    } \
    asm volatile("cp.async.commit_group;"); \
} while (0)

#pragma unroll
    for (int s = 0; s < STAGES - 1; s++) LOAD_STAGE(s, s);

    for (int kt = 0; kt < kIters; kt++) {
        asm volatile("cp.async.wait_group %0;" :: "n"(STAGES - 2) : "memory");
        __syncthreads();
        LOAD_STAGE((kt + STAGES - 1) & (STAGES - 1), kt + STAGES - 1);
        int st = kt & (STAGES - 1);
        uint32_t baseA = su + st * 16384;
        uint32_t baseB = baseA + 8192;
#pragma unroll
        for (int ks = 0; ks < 2; ks++) {
            int lr16 = lane & 15;
            int ach = ks * 2 + (lane >> 4);
            uint32_t afr[2][4];
#pragma unroll
            for (int mf = 0; mf < 2; mf++) {
                int r = warp_m * 32 + mf * 16 + lr16;
                ldsm4(afr[mf], baseA + r * 64 + ((ach ^ ((r >> 1) & 3)) * 16));
            }
#pragma unroll
            for (int np = 0; np < 4; np++) {
                int r = warp_n * 64 + np * 16 + lr16;
                uint32_t bfr[4];
                ldsm4(bfr, baseB + r * 64 + ((ach ^ ((r >> 1) & 3)) * 16));
                uint32_t b0[2] = {bfr[0], bfr[2]};
                uint32_t b1[2] = {bfr[1], bfr[3]};
#pragma unroll
                for (int mf = 0; mf < 2; mf++) {
                    mma16816(acc[mf][np * 2], afr[mf], b0);
                    mma16816(acc[mf][np * 2 + 1], afr[mf], b1);
                }
            }
        }
    }

    // epilogue
    int trow = lane >> 2, tc2 = (lane & 3) * 2;
#pragma unroll
    for (int mf = 0; mf < 2; mf++) {
#pragma unroll
        for (int nf = 0; nf < 8; nf++) {
            int n = n0 + warp_n * 64 + nf * 8 + tc2;
            int m = m0 + warp_m * 32 + mf * 16 + trow;
#pragma unroll
            for (int hh = 0; hh < 2; hh++) {
                float v0 = acc[mf][nf][hh * 2];
                float v1 = acc[mf][nf][hh * 2 + 1];
                int mr = m + hh * 8;
                if (EPI == 1) {
                    v0 = softplus_f(v0 + bias[n]);
                    v1 = softplus_f(v1 + bias[n + 1]);
                }
                if (EPI == 3) {
                    if (n < N)     atomicAdd(&C[(size_t)mr * ldc + n], v0);
                    if (n + 1 < N) atomicAdd(&C[(size_t)mr * ldc + n + 1], v1);
                } else {
                    *reinterpret_cast<float2*>(&C[(size_t)mr * ldc + n]) =
                        make_float2(v0, v1);
                }
            }
        }
    }
#undef LOAD_STAGE
}

// ---------------- selective scan: 2 channels/warp, 2-deferred reduction ----
__global__ void __launch_bounds__(256) scan_k(
    const float* __restrict__ delta, const float* __restrict__ xc,
    const float* __restrict__ xdbl, const float* __restrict__ xz,
    const float* __restrict__ A_log, const float* __restrict__ dski,
    __nv_bfloat16* __restrict__ ye) {
    int warp = (blockIdx.x * blockDim.x + threadIdx.x) >> 5;
    int lane = threadIdx.x & 31;
    int half = lane >> 4;
    int s = lane & 15;
    int c = warp * 2 + half;
    if (c >= BSZ * DI) return;
    int b = c / DI;
    int d = c % DI;

    float As = -__expf(A_log[d * DS + s]);
    float dsk = dski[d];
    float h = 0.f;
    const float* drow = delta + (size_t)b * LSZ * DI + d;
    const float* urow = xc + (size_t)b * LSZ * DI + d;
    const float* zrow = xz + (size_t)b * LSZ * (2 * DI) + DI + d;
    const float* xd = xdbl + (size_t)b * LSZ * XPN;
    __nv_bfloat16* yr = ye + (size_t)b * LSZ * KE_BIG + d;

    // prefetch step 0
    float dl = drow[0];
    float u  = urow[0];
    float bm = xd[DTR + s];
    float cm = xd[DTR + DS + s];
    float z  = zrow[0];

    float praw = 0.f, ppart = 0.f;    // raw p (step l-1), partial p (step l-2)
    float u1 = 0.f, z1 = 0.f, u2 = 0.f, z2 = 0.f;

#pragma unroll 2
    for (int l = 0; l < LSZ; l++) {
        // stage-1 reduction of step l-1, stage-2 of step l-2 (interleaved)
        float a8 = __shfl_xor_sync(0xffffffffu, praw, 8);
        float b2 = __shfl_xor_sync(0xffffffffu, ppart, 2);
        float dA = __expf(dl * As);
        float dlu = dl * u;
        praw += a8;
        ppart += b2;
        // prefetch l+1
        float dln = 0.f, un = 0.f, bmn = 0.f, cmn = 0.f, zn = 0.f;
        if (l < LSZ - 1) {
            dln = drow[(size_t)(l + 1) * DI];
            un  = urow[(size_t)(l + 1) * DI];
            bmn = xd[(size_t)(l + 1) * XPN + DTR + s];
            cmn = xd[(size_t)(l + 1) * XPN + DTR + DS + s];
            zn  = zrow[(size_t)(l + 1) * (2 * DI)];
        }
        float a4 = __shfl_xor_sync(0xffffffffu, praw, 4);
        float b1 = __shfl_xor_sync(0xffffffffu, ppart, 1);
        h = dA * h + dlu * bm;
        float pnew = h * cm;
        praw += a4;
        ppart += b1;
        if (l >= 2 && s == 0) {
            float yv = (ppart + u2 * dsk) * (z2 / (1.f + __expf(-z2)));
            __nv_bfloat16 hh, ll; bsplit(yv, hh, ll);
            __nv_bfloat16* yp = yr + (size_t)(l - 2) * KE_BIG;
            yp[0] = hh; yp[DI] = hh; yp[2 * DI] = ll;
        }
        ppart = praw; praw = pnew;
        u2 = u1; z2 = z1; u1 = u; z1 = z;
        dl = dln; u = un; bm = bmn; cm = cmn; z = zn;
    }
    // drain: ppart = partial(step LSZ-2), praw = raw(step LSZ-1)
    ppart += __shfl_xor_sync(0xffffffffu, ppart, 2);
    ppart += __shfl_xor_sync(0xffffffffu, ppart, 1);
    praw += __shfl_xor_sync(0xffffffffu, praw, 8);
    praw += __shfl_xor_sync(0xffffffffu, praw, 4);
    praw += __shfl_xor_sync(0xffffffffu, praw, 2);
    praw += __shfl_xor_sync(0xffffffffu, praw, 1);
    if (s == 0) {
        float yv = (ppart + u2 * dsk) * (z2 / (1.f + __expf(-z2)));
        __nv_bfloat16 hh, ll; bsplit(yv, hh, ll);
        __nv_bfloat16* yp = yr + (size_t)(LSZ - 2) * KE_BIG;
        yp[0] = hh; yp[DI] = hh; yp[2 * DI] = ll;
        yv = (praw + u1 * dsk) * (z1 / (1.f + __expf(-z1)));
        bsplit(yv, hh, ll);
        yp = yr + (size_t)(LSZ - 1) * KE_BIG;
        yp[0] = hh; yp[DI] = hh; yp[2 * DI] = ll;
    }
}

// ---------------- final: last-token rmsnorm ----------------
__global__ void final_k(const float* __restrict__ resid, const float* __restrict__ nw,
                        const int* __restrict__ mask, float* __restrict__ out) {
    int b = blockIdx.x;
    float ms = 0.f;
    for (int i = threadIdx.x; i < LSZ; i += blockDim.x) ms += (float)mask[b * LSZ + i];
    ms = block_sum(ms);
    int last = (int)(ms + 0.5f) - 1;
    const float* xr = resid + ((size_t)b * LSZ + last) * DM;
    float sacc = 0.f;
    for (int cidx = threadIdx.x; cidx < DM; cidx += blockDim.x) {
        float v = xr[cidx];
        sacc += v * v;
    }
    sacc = block_sum(sacc);
    float inv = rsqrtf(sacc / (float)DM + 1e-5f);
    for (int cidx = threadIdx.x; cidx < DM; cidx += blockDim.x)
        out[b * DM + cidx] = xr[cidx] * inv * nw[cidx];
}

// ---------------- driver ----------------
extern "C" void kernel_launch(void* const* d_in, const int* in_sizes, int n_in,
                              void* d_out, int out_size) {
    const int*   seq       = (const int*)d_in[0];
    const int*   mask      = (const int*)d_in[1];
    const float* emb       = (const float*)d_in[2];
    const float* norm_w    = (const float*)d_in[3];
    const float* in_proj_w = (const float*)d_in[4];
    const float* conv_w    = (const float*)d_in[5];
    const float* conv_b    = (const float*)d_in[6];
    const float* x_proj_w  = (const float*)d_in[7];
    const float* dt_w      = (const float*)d_in[8];
    const float* dt_b      = (const float*)d_in[9];
    const float* A_log     = (const float*)d_in[10];
    const float* D_skip    = (const float*)d_in[11];
    const float* out_w     = (const float*)d_in[12];
    const float* normf_w   = (const float*)d_in[13];

    float *resid, *xz, *xc, *xdbl, *delta;
    __nv_bfloat16 *ae;
    cudaGetSymbolAddress((void**)&resid, g_resid);
    cudaGetSymbolAddress((void**)&xz,    g_xz);
    cudaGetSymbolAddress((void**)&xc,    g_xc);
    cudaGetSymbolAddress((void**)&xdbl,  g_xdbl);
    cudaGetSymbolAddress((void**)&delta, g_delta);
    cudaGetSymbolAddress((void**)&ae,    g_aext);
    __nv_bfloat16 *wi, *wo, *wx, *wd;
    cudaGetSymbolAddress((void**)&wi, g_wi);
    cudaGetSymbolAddress((void**)&wo, g_wo);
    cudaGetSymbolAddress((void**)&wx, g_wx);
    cudaGetSymbolAddress((void**)&wd, g_wd);

    cudaFuncSetAttribute(gemm_bf<0>, cudaFuncAttributeMaxDynamicSharedMemorySize, GSMEM);
    cudaFuncSetAttribute(gemm_bf<1>, cudaFuncAttributeMaxDynamicSharedMemorySize, GSMEM);
    cudaFuncSetAttribute(gemm_bf<3>, cudaFuncAttributeMaxDynamicSharedMemorySize, GSMEM);

    embed_k<<<(ROWS * (DM / 4) + 255) / 256, 256>>>(seq, emb, resid);

    // ---- all weight-ext preps upfront (independent, overlap each other) ----
    for (int i = 0; i < NL; i++) {
        wprep_k<<<(2 * DI * DM + 255) / 256, 256>>>(
            in_proj_w + (size_t)i * 2 * DI * DM, wi + (size_t)i * (2 * DI) * KE_IN,
            2 * DI, 2 * DI, DM, DM);
        wprep_k<<<(DM * DI + 255) / 256, 256>>>(
            out_w + (size_t)i * DM * DI, wo + (size_t)i * DM * KE_BIG,
            DM, DM, DI, DI);
        wprep_k<<<(128 * DI + 255) / 256, 256>>>(
            x_proj_w + (size_t)i * XPN * DI, wx + (size_t)i * 128 * KE_BIG,
            XPN, 128, DI, DI);
        wprep_k<<<(DI * 64 + 255) / 256, 256>>>(
            dt_w + (size_t)i * DI * DTR, wd + (size_t)i * DI * KE_DT,
            DI, DI, DTR, 64);
    }

    for (int i = 0; i < NL; i++) {
        rmsnorm_k<<<ROWS, 256>>>(resid, norm_w + i * DM, ae);
        // in_proj: xz = hn @ W^T   (N=3072, Kext=2304, 72 iters)
        gemm_bf<0><<<dim3(24, 16, 1), 256, GSMEM>>>(
            ae, wi + (size_t)i * (2 * DI) * KE_IN, xz, nullptr,
            KE_IN, KE_IN / 32, 2 * DI, 2 * DI);

        conv_silu_k<<<(ROWS * DI) / 256, 256>>>(
            xz, conv_w + i * DI * 4, conv_b + i * DI, xc, ae);

        // x_proj: xdbl = xc @ W^T  (N=80 pad 128, Kext=4608, split-K z=16)
        cudaMemsetAsync(xdbl, 0, (size_t)ROWS * XPN * sizeof(float));
        gemm_bf<3><<<dim3(1, 16, 16), 256, GSMEM>>>(
            ae, wx + (size_t)i * 128 * KE_BIG, xdbl, nullptr,
            KE_BIG, KE_BIG / (16 * 32), XPN, XPN);

        // dt: delta = softplus(xdbl[:, :48] @ dt_w^T + dt_b)
        dtprep_k<<<(ROWS * 64 + 255) / 256, 256>>>(xdbl, ae);
        gemm_bf<1><<<dim3(12, 16, 1), 256, GSMEM>>>(
            ae, wd + (size_t)i * DI * KE_DT, delta, dt_b + i * DI,
            KE_DT, KE_DT / 32, DI, DI);

        // selective scan -> y ext (Kext=4608)
        scan_k<<<(BSZ * DI / 2 * 32) / 256, 256>>>(
            delta, xc, xdbl, xz, A_log + i * DI * DS, D_skip + i * DI, ae);

        // out_proj: resid += y @ W^T  (N=768, Kext=4608, split-K z=3, atomics)
        gemm_bf<3><<<dim3(6, 16, 3), 256, GSMEM>>>(
            ae, wo + (size_t)i * DM * KE_BIG, resid, nullptr,
            KE_BIG, KE_BIG / (3 * 32), DM, DM);
    }

    final_k<<<BSZ, 256>>>(resid, normf_w, mask, (float*)d_out);
}